// round 2
// baseline (speedup 1.0000x reference)
#include <cuda_runtime.h>
#include <cuda_bf16.h>
#include <cstdint>

// Problem constants (match reference)
#define NGRID        512
#define X0_C         1.0f
#define XMAX_C       10.0f
// DX = (XMAX - X0) / (NGRID - 1) = 9/511
#define DX_C         ((XMAX_C - X0_C) / (float)(NGRID - 1))
#define E_EDGES      2000000
#define N_NODES      500000
#define NUM_INGRLS   16
#define N_ONSITE     4

// Output layout in d_out (float32), concatenated in reference return order:
//   [0, 32M)        edge_features  [E, 16]
//   [32M, 64M)      edge_overlap   [E, 16]
//   [64M, 66M)      node_features  [N, 4]
#define EDGE_OUT_ELEMS   ((long long)E_EDGES * NUM_INGRLS)      // 32,000,000
#define NODE_OUT_BASE    (2LL * EDGE_OUT_ELEMS)                 // 64,000,000

// ---------------------------------------------------------------------------
// Edge kernel: one thread per (edge, quartet-of-4-integrals).
// Per thread: 1 rij + 1 etype load (L1-broadcast across the 4 quartets),
// 16 independent table loads (L2-resident: tables are 640KB total),
// 2 coalesced float4 stores (hopping + overlap outputs).
// ---------------------------------------------------------------------------
__global__ void __launch_bounds__(256) dftbsk_edges_kernel(
    const float*  __restrict__ rij,
    const int*    __restrict__ edge_type,
    const float*  __restrict__ hopping_tables,   // [B,16,512]
    const float*  __restrict__ overlap_tables,   // [B,16,512]
    float*        __restrict__ out,              // d_out base
    int n_edges)
{
    int idx = blockIdx.x * blockDim.x + threadIdx.x;   // [0, n_edges*4)
    int e = idx >> 2;
    if (e >= n_edges) return;
    int m_base = (idx & 3) << 2;                        // 0,4,8,12

    float r = __ldg(&rij[e]);
    int   b = __ldg(&edge_type[e]);

    float t = (r - X0_C) * (1.0f / DX_C);
    int i0 = (int)floorf(t);
    i0 = min(max(i0, 0), NGRID - 2);
    float frac  = t - (float)i0;
    float omf   = 1.0f - frac;

    // Base row pointers for this bond type
    const float* hbase = hopping_tables + (size_t)b * (NUM_INGRLS * NGRID);
    const float* obase = overlap_tables + (size_t)b * (NUM_INGRLS * NGRID);

    float4 hv, ov;
    {
        const float* h0p = hbase + (size_t)(m_base + 0) * NGRID + i0;
        const float* h1p = hbase + (size_t)(m_base + 1) * NGRID + i0;
        const float* h2p = hbase + (size_t)(m_base + 2) * NGRID + i0;
        const float* h3p = hbase + (size_t)(m_base + 3) * NGRID + i0;
        const float* o0p = obase + (size_t)(m_base + 0) * NGRID + i0;
        const float* o1p = obase + (size_t)(m_base + 1) * NGRID + i0;
        const float* o2p = obase + (size_t)(m_base + 2) * NGRID + i0;
        const float* o3p = obase + (size_t)(m_base + 3) * NGRID + i0;

        // Issue all 16 loads before consuming (MLP)
        float h0a = __ldg(h0p),     h0b = __ldg(h0p + 1);
        float h1a = __ldg(h1p),     h1b = __ldg(h1p + 1);
        float h2a = __ldg(h2p),     h2b = __ldg(h2p + 1);
        float h3a = __ldg(h3p),     h3b = __ldg(h3p + 1);
        float o0a = __ldg(o0p),     o0b = __ldg(o0p + 1);
        float o1a = __ldg(o1p),     o1b = __ldg(o1p + 1);
        float o2a = __ldg(o2p),     o2b = __ldg(o2p + 1);
        float o3a = __ldg(o3p),     o3b = __ldg(o3p + 1);

        hv.x = h0a * omf + h0b * frac;
        hv.y = h1a * omf + h1b * frac;
        hv.z = h2a * omf + h2b * frac;
        hv.w = h3a * omf + h3b * frac;
        ov.x = o0a * omf + o0b * frac;
        ov.y = o1a * omf + o1b * frac;
        ov.z = o2a * omf + o2b * frac;
        ov.w = o3a * omf + o3b * frac;
    }

    // Coalesced float4 stores: idx*4 floats into each output block
    float4* out_h = (float4*)out;                                // edge_features
    float4* out_o = (float4*)(out + EDGE_OUT_ELEMS);             // edge_overlap
    out_h[idx] = hv;
    out_o[idx] = ov;
}

// ---------------------------------------------------------------------------
// Node kernel: one thread per node; onsiteE row is 16B -> float4 gather/store.
// ---------------------------------------------------------------------------
__global__ void __launch_bounds__(256) dftbsk_nodes_kernel(
    const int*    __restrict__ atom_type,
    const float*  __restrict__ onsiteE,          // [A, 4], 16B-aligned rows
    float*        __restrict__ out_nodes,        // d_out + 64M
    int n_nodes)
{
    int n = blockIdx.x * blockDim.x + threadIdx.x;
    if (n >= n_nodes) return;
    int a = __ldg(&atom_type[n]);
    float4 v = __ldg((const float4*)onsiteE + a);
    ((float4*)out_nodes)[n] = v;
}

extern "C" void kernel_launch(void* const* d_in, const int* in_sizes, int n_in,
                              void* d_out, int out_size)
{
    const float* rij            = (const float*)d_in[0];
    const int*   edge_type      = (const int*)  d_in[1];
    const int*   atom_type      = (const int*)  d_in[2];
    const float* hopping_tables = (const float*)d_in[3];
    const float* overlap_tables = (const float*)d_in[4];
    const float* onsiteE        = (const float*)d_in[5];
    float*       out            = (float*)d_out;

    int n_edges = in_sizes[0];
    int n_nodes = in_sizes[2];

    {
        int total = n_edges * 4;                    // 8M threads
        int threads = 256;
        int blocks = (total + threads - 1) / threads;
        dftbsk_edges_kernel<<<blocks, threads>>>(
            rij, edge_type, hopping_tables, overlap_tables, out, n_edges);
    }
    {
        int threads = 256;
        int blocks = (n_nodes + threads - 1) / threads;
        dftbsk_nodes_kernel<<<blocks, threads>>>(
            atom_type, onsiteE, out + NODE_OUT_BASE, n_nodes);
    }
}

// round 7
// speedup vs baseline: 4.9407x; 4.9407x over previous
#include <cuda_runtime.h>
#include <cuda_bf16.h>
#include <cstdint>

// Problem constants (match reference)
#define NGRID        512
#define X0_C         1.0f
#define XMAX_C       10.0f
#define DX_C         ((XMAX_C - X0_C) / (float)(NGRID - 1))   // 9/511
#define N_BOND_TYPES 10
#define NUM_INGRLS   16
#define E_EDGES      2000000
#define N_NODES      500000

// Output layout in d_out (float32), reference return order:
//   [0, 32M)    edge_features [E,16]
//   [32M, 64M)  edge_overlap  [E,16]
//   [64M, 66M)  node_features [N,4]
#define EDGE_OUT_ELEMS   ((long long)E_EDGES * NUM_INGRLS)
#define NODE_OUT_BASE    (2LL * EDGE_OUT_ELEMS)

// Transposed tables: [B][G][M] so one (b,i0) row is 16 contiguous floats (64B).
// 10*512*16*4 = 327,680 bytes each. __device__ globals = legal scratch.
__device__ float g_hopT[N_BOND_TYPES * NGRID * NUM_INGRLS];
__device__ float g_ovlT[N_BOND_TYPES * NGRID * NUM_INGRLS];

// ---------------------------------------------------------------------------
// Transpose kernel: [B,M,G] -> [B,G,M] for both tables. Tiny (163,840 elems).
// ---------------------------------------------------------------------------
__global__ void __launch_bounds__(256) dftbsk_transpose_kernel(
    const float* __restrict__ hopping_tables,
    const float* __restrict__ overlap_tables)
{
    int idx = blockIdx.x * blockDim.x + threadIdx.x;
    const int total = N_BOND_TYPES * NUM_INGRLS * NGRID;
    if (idx >= total) return;
    // idx enumerates source layout [B][M][G] with g fastest -> coalesced reads
    int g = idx & (NGRID - 1);
    int bm = idx >> 9;               // b*16 + m
    int m = bm & (NUM_INGRLS - 1);
    int b = bm >> 4;
    int dst = (b * NGRID + g) * NUM_INGRLS + m;
    g_hopT[dst] = hopping_tables[idx];
    g_ovlT[dst] = overlap_tables[idx];
}

// ---------------------------------------------------------------------------
// Edge kernel: 4 threads per edge (one per quartet of integrals).
// Per thread: rij/etype load (L1-broadcast within the 4), then 4x LDG.128
// from the transposed L2-resident tables, 8 FMAs, 2 coalesced float4 stores.
// ---------------------------------------------------------------------------
__global__ void __launch_bounds__(256) dftbsk_edges_kernel(
    const float* __restrict__ rij,
    const int*   __restrict__ edge_type,
    float*       __restrict__ out,
    int n_edges)
{
    int idx = blockIdx.x * blockDim.x + threadIdx.x;   // [0, n_edges*4)
    int e = idx >> 2;
    if (e >= n_edges) return;
    int q = idx & 3;                                   // quartet index

    float r = __ldg(&rij[e]);
    int   b = __ldg(&edge_type[e]);

    float t = (r - X0_C) * (1.0f / DX_C);
    int i0 = (int)floorf(t);
    i0 = min(max(i0, 0), NGRID - 2);
    float frac = t - (float)i0;
    float omf  = 1.0f - frac;

    // Row base in transposed layout; rows are 16 floats = 4 float4.
    size_t row = (size_t)(b * NGRID + i0) * (NUM_INGRLS / 4);  // in float4 units
    const float4* hrow = (const float4*)g_hopT + row;
    const float4* orow = (const float4*)g_ovlT + row;

    // Issue all 4 wide loads up front (MLP); i0+1 row is +4 float4.
    float4 h0 = __ldg(hrow + q);
    float4 h1 = __ldg(hrow + 4 + q);
    float4 o0 = __ldg(orow + q);
    float4 o1 = __ldg(orow + 4 + q);

    float4 hv, ov;
    hv.x = h0.x * omf + h1.x * frac;
    hv.y = h0.y * omf + h1.y * frac;
    hv.z = h0.z * omf + h1.z * frac;
    hv.w = h0.w * omf + h1.w * frac;
    ov.x = o0.x * omf + o1.x * frac;
    ov.y = o0.y * omf + o1.y * frac;
    ov.z = o0.z * omf + o1.z * frac;
    ov.w = o0.w * omf + o1.w * frac;

    float4* out_h = (float4*)out;
    float4* out_o = (float4*)(out + EDGE_OUT_ELEMS);
    out_h[idx] = hv;      // fully coalesced
    out_o[idx] = ov;
}

// ---------------------------------------------------------------------------
// Node kernel: 4 nodes per thread (int4 type load, 4x float4 gather/store).
// onsiteE is 4x4 floats = 64B, L1-resident.
// ---------------------------------------------------------------------------
__global__ void __launch_bounds__(256) dftbsk_nodes_kernel(
    const int*   __restrict__ atom_type,
    const float* __restrict__ onsiteE,
    float*       __restrict__ out_nodes,
    int n_nodes)
{
    int t = blockIdx.x * blockDim.x + threadIdx.x;
    int n0 = t * 4;
    if (n0 >= n_nodes) return;

    const float4* on = (const float4*)onsiteE;
    float4* outv = (float4*)out_nodes;

    if (n0 + 4 <= n_nodes) {
        int4 a = __ldg((const int4*)atom_type + t);
        float4 v0 = __ldg(on + a.x);
        float4 v1 = __ldg(on + a.y);
        float4 v2 = __ldg(on + a.z);
        float4 v3 = __ldg(on + a.w);
        outv[n0 + 0] = v0;
        outv[n0 + 1] = v1;
        outv[n0 + 2] = v2;
        outv[n0 + 3] = v3;
    } else {
        for (int n = n0; n < n_nodes; n++) {
            int a = __ldg(&atom_type[n]);
            outv[n] = __ldg(on + a);
        }
    }
}

extern "C" void kernel_launch(void* const* d_in, const int* in_sizes, int n_in,
                              void* d_out, int out_size)
{
    const float* rij            = (const float*)d_in[0];
    const int*   edge_type      = (const int*)  d_in[1];
    const int*   atom_type      = (const int*)  d_in[2];
    const float* hopping_tables = (const float*)d_in[3];
    const float* overlap_tables = (const float*)d_in[4];
    // d_in[5] = onsiteE
    const float* onsiteE        = (const float*)d_in[5];
    float*       out            = (float*)d_out;

    int n_edges = in_sizes[0];
    int n_nodes = in_sizes[2];

    {
        const int total = N_BOND_TYPES * NUM_INGRLS * NGRID;
        dftbsk_transpose_kernel<<<(total + 255) / 256, 256>>>(
            hopping_tables, overlap_tables);
    }
    {
        int total = n_edges * 4;
        dftbsk_edges_kernel<<<(total + 255) / 256, 256>>>(
            rij, edge_type, out, n_edges);
    }
    {
        int threads_needed = (n_nodes + 3) / 4;
        dftbsk_nodes_kernel<<<(threads_needed + 255) / 256, 256>>>(
            atom_type, onsiteE, out + NODE_OUT_BASE, n_nodes);
    }
}